// round 6
// baseline (speedup 1.0000x reference)
#include <cuda_runtime.h>

// out[b,o,d0,p1,p2,p3] = bias[o]
//   + sum_{i,c,k1,k2,k3} w[i,o,c,k1,k2,k3] * xp[b, L/26, L%26, p1+k1, p2+k2, p3+k3],  L=(d0+i)*32+c
// xp = x zero-padded by 1 on all four spatial dims (reference's reshape scrambles (Ci,D0p)).
// x(2,32,24,24,24,24) f32, w(3,64,32,3,3,3) f32, bias(64) f32, out(2,64,24,24,24,24) f32.

#define DDIM 24
#define CI 32
#define CO 64
#define OCB 16
#define NITER 96
#define SLOTS 6
#define XSL 2028            // 3*676 floats per L
#define WSL 216             // float2 per L (16 oc x 27 taps interleaved as 8 pairs)

typedef unsigned long long u64;

__device__ __forceinline__ u64 pack_dup(float a) {
    u64 r;
    unsigned ai = __float_as_uint(a);
    asm("mov.b64 %0, {%1, %1};" : "=l"(r) : "r"(ai));
    return r;
}
__device__ __forceinline__ void fma2(u64 &acc, u64 x, u64 wv) {
    asm("fma.rn.f32x2 %0, %1, %2, %0;" : "+l"(acc) : "l"(x), "l"(wv));
}
__device__ __forceinline__ void unpack2(u64 v, float &lo, float &hi) {
    unsigned l, h;
    asm("mov.b64 {%0, %1}, %2;" : "=r"(l), "=r"(h) : "l"(v));
    lo = __uint_as_float(l); hi = __uint_as_float(h);
}
__device__ __forceinline__ void cpasync4(const float* smem_dst, const float* gsrc, unsigned srcsz) {
    unsigned a = (unsigned)__cvta_generic_to_shared(smem_dst);
    asm volatile("cp.async.ca.shared.global [%0], [%1], 4, %2;"
                 :: "r"(a), "l"(gsrc), "r"(srcsz) : "memory");
}
__device__ __forceinline__ void cp_commit() {
    asm volatile("cp.async.commit_group;" ::: "memory");
}
__device__ __forceinline__ void cp_wait2() {
    asm volatile("cp.async.wait_group 2;" ::: "memory");
}

// stage one L into its ring slot via cp.async (zfill for padding / invalid frames)
__device__ __forceinline__ void stage_L(int Lk, int L0, int b,
                                        const float* __restrict__ x,
                                        const float* __restrict__ w,
                                        const int* xoff, unsigned xmask,
                                        const int* wgoff, const int* wsts, unsigned wok,
                                        float* xs, float2* wv2, int tid)
{
    if (Lk < NITER) {
        const int slot = Lk % SLOTS;
        const int Labs = L0 + Lk;
        const int cin  = Labs / 26;
        const int e0p  = Labs - cin * 26;
        const bool fok = (unsigned)(e0p - 1) < (unsigned)DDIM;
        const float* xrow = x + ((size_t)(b * CI + cin) * DDIM + (fok ? e0p - 1 : 0)) * 13824;
        float* xd = xs + slot * XSL;
        #pragma unroll
        for (int k = 0; k < 8; k++) {
            const int idx = tid + k * 256;
            if (idx < XSL) {
                const unsigned sz = (fok && ((xmask >> k) & 1)) ? 4u : 0u;
                cpasync4(xd + idx, xrow + xoff[k], sz);
            }
        }
        const int i = Lk >> 5;
        const int c = Labs & 31;
        const float* wb = w + i * 55296 + c * 27;
        float* wd = (float*)(wv2 + slot * WSL);
        #pragma unroll
        for (int k = 0; k < 2; k++)
            if ((wok >> k) & 1) cpasync4(wd + wsts[k], wb + wgoff[k], 4u);
    }
    cp_commit();   // always commit (possibly empty) to keep group counting uniform
}

// compute one L from ring slot: 486 FFMA2 per thread
__device__ __forceinline__ void compute_L(const float* xsl0, const float2* wslot,
                                          int ty, int rb, int cb, u64 acc2[2][9])
{
    #pragma unroll
    for (int k1 = 0; k1 < 3; k1++) {
        u64 wp0[9], wp1[9];
        const u64* wr0 = (const u64*)&wslot[0] + (size_t)((ty * 2 + 0) * 27 + k1 * 9);
        const u64* wr1 = (const u64*)&wslot[0] + (size_t)((ty * 2 + 1) * 27 + k1 * 9);
        #pragma unroll
        for (int t = 0; t < 9; t++) { wp0[t] = wr0[t]; wp1[t] = wr1[t]; }

        const float* xsl = xsl0 + k1 * 676 + rb * 78 + cb * 3;
        #pragma unroll
        for (int r = 0; r < 5; r++) {
            #pragma unroll
            for (int s = 0; s < 5; s++) {
                const u64 x2 = pack_dup(xsl[r * 26 + s]);
                #pragma unroll
                for (int k2 = (r > 2 ? r - 2 : 0); k2 <= (r < 2 ? r : 2); k2++) {
                    #pragma unroll
                    for (int k3 = (s > 2 ? s - 2 : 0); k3 <= (s < 2 ? s : 2); k3++) {
                        const int pos = (r - k2) * 3 + (s - k3);
                        const int t   = k2 * 3 + k3;
                        fma2(acc2[0][pos], x2, wp0[t]);
                        fma2(acc2[1][pos], x2, wp1[t]);
                    }
                }
            }
        }
    }
}

__global__ __launch_bounds__(256, 2)
void conv4d_kernel(const float* __restrict__ x,
                   const float* __restrict__ w,
                   const float* __restrict__ bias,
                   float* __restrict__ out)
{
    extern __shared__ float smem_dyn[];
    float*  xs  = smem_dyn;                          // SLOTS * 2028 floats
    float2* wv2 = (float2*)(smem_dyn + SLOTS * XSL); // SLOTS * 216 float2

    const int blk = blockIdx.x;          // b*576 + d0*24 + d1
    const int d1  = blk % DDIM;
    const int t0  = blk / DDIM;
    const int d0  = t0 % DDIM;
    const int b   = t0 / DDIM;
    const int oc0 = blockIdx.y * OCB;

    const int tid = threadIdx.x;
    const int tx  = tid & 63;
    const int ty  = tid >> 6;
    const int rb  = tx >> 3;             // d2 block (rows rb*3..rb*3+2)
    const int cb  = tx & 7;              // d3 block (cols cb*3..cb*3+2)

    // ---- loop-invariant staging metadata ----
    int xoff[8]; unsigned xmask = 0;
    #pragma unroll
    for (int k = 0; k < 8; k++) {
        const int idx = tid + k * 256;
        const int s   = idx / 676, rem = idx - s * 676;
        const int r   = rem / 26,  c_  = rem - r * 26;
        const int e1  = d1 + s - 1, p2 = r - 1, p3 = c_ - 1;
        const bool ok = (idx < XSL) && (unsigned)e1 < DDIM &&
                        (unsigned)p2 < DDIM && (unsigned)p3 < DDIM;
        xoff[k] = ok ? (e1 * 576 + p2 * 24 + p3) : 0;
        if (ok) xmask |= 1u << k;
    }
    int wgoff[2], wsts[2]; unsigned wok = 0;
    #pragma unroll
    for (int k = 0; k < 2; k++) {
        const int e = tid + k * 256;
        const int ocl = e / 27, t = e - ocl * 27;
        if (e < 432) wok |= 1u << k;
        wgoff[k] = (oc0 + ocl) * (CI * 27) + t;               // + i*55296 + c*27
        wsts[k]  = (ocl >> 1) * 54 + t * 2 + (ocl & 1);       // float index into slot
    }

    u64 acc2[2][9];
    #pragma unroll
    for (int p = 0; p < 2; p++)
        #pragma unroll
        for (int q = 0; q < 9; q++) acc2[p][q] = 0ull;

    const int L0 = d0 * 32;

    // ---- prologue: stage L0..L3 (4 groups in flight) ----
    #pragma unroll
    for (int Lk = 0; Lk < 4; Lk++)
        stage_L(Lk, L0, b, x, w, xoff, xmask, wgoff, wsts, wok, xs, wv2, tid);

    // ---- main loop: 48 epochs of 2 L each, one barrier per epoch ----
    for (int e = 0; e < NITER / 2; e++) {
        const int Lk = 2 * e;
        cp_wait2();           // L=Lk, Lk+1 complete (2 newer groups may be pending)
        __syncthreads();

        // issue prefetch for Lk+4, Lk+5 (their slots were consumed in epoch e-1)
        stage_L(Lk + 4, L0, b, x, w, xoff, xmask, wgoff, wsts, wok, xs, wv2, tid);
        stage_L(Lk + 5, L0, b, x, w, xoff, xmask, wgoff, wsts, wok, xs, wv2, tid);

        // compute the two ready L values
        #pragma unroll
        for (int t = 0; t < 2; t++) {
            const int La   = L0 + Lk + t;
            const int e0p  = La % 26;
            if ((unsigned)(e0p - 1) < (unsigned)DDIM) {
                const int slot = (Lk + t) % SLOTS;
                compute_L(xs + slot * XSL, wv2 + slot * WSL, ty, rb, cb, acc2);
            }
        }
    }

    // ---- epilogue: unpack, add bias, store ----
    #pragma unroll
    for (int p = 0; p < 2; p++) {
        const int oce = oc0 + ty * 4 + p * 2;       // even oc of the pair
        const float bv0 = bias[oce];
        const float bv1 = bias[oce + 1];
        const size_t ob0 = ((size_t)(b * CO + oce) * 576 + d0 * 24 + d1) * 576;
        const size_t ob1 = ob0 + (size_t)331776;    // next oc: +576*576
        #pragma unroll
        for (int ii = 0; ii < 3; ii++) {
            #pragma unroll
            for (int jj = 0; jj < 3; jj++) {
                float lo, hi;
                unpack2(acc2[p][ii * 3 + jj], lo, hi);
                const int po = (rb * 3 + ii) * 24 + cb * 3 + jj;
                out[ob0 + po] = lo + bv0;
                out[ob1 + po] = hi + bv1;
            }
        }
    }
}

extern "C" void kernel_launch(void* const* d_in, const int* in_sizes, int n_in,
                              void* d_out, int out_size)
{
    const float* x = nullptr;
    const float* w = nullptr;
    const float* bias = nullptr;
    for (int k = 0; k < n_in; k++) {
        if (in_sizes[k] == 2 * 32 * 24 * 24 * 24 * 24) x    = (const float*)d_in[k];
        else if (in_sizes[k] == 3 * 64 * 32 * 27)      w    = (const float*)d_in[k];
        else if (in_sizes[k] == 64)                    bias = (const float*)d_in[k];
    }
    float* out = (float*)d_out;

    const int smem_bytes = SLOTS * XSL * 4 + SLOTS * WSL * 8;  // 59040
    cudaFuncSetAttribute(conv4d_kernel, cudaFuncAttributeMaxDynamicSharedMemorySize, smem_bytes);

    dim3 grid(2 * 24 * 24, CO / OCB);   // (1152, 4)
    dim3 block(256);
    conv4d_kernel<<<grid, block, smem_bytes>>>(x, w, bias, out);
}

// round 8
// speedup vs baseline: 2.2516x; 2.2516x over previous
#include <cuda_runtime.h>
#include <cstdint>

// out[b,o,d0,d1,p2,p3] = bias[o] + sum_{chunk,l,k1,k2,k3} w[chunk,o,l,k1,k2,k3] *
//   xp[b, cin, e0, d1+k1-1, p2+k2-1, p3+k3-1],  Labs=(d0+chunk)*32+l, cin=Labs/26, e0=Labs%26-1
// Implicit GEMM per (b,d0,d1): D[640 anchors][64 oc], K=2592, via mma.sync tf32 (legacy tensor path).

#define DDIM 24
#define AROWS 694                 // 676 plane rows + 18 junk-pad rows (zeroed)
#define AFL (AROWS * 32)          // floats in A buffer
#define BFL (9 * 2048)            // 9 taps x 64 oc x 32 l

__device__ float W2d[165888];     // [(chunk*3+k1)*9+tap][oc][l], tf32-rounded

__device__ __forceinline__ void cpasync16(const float* smem_dst, const float* gsrc) {
    unsigned a = (unsigned)__cvta_generic_to_shared(smem_dst);
    asm volatile("cp.async.cg.shared.global [%0], [%1], 16;" :: "r"(a), "l"(gsrc) : "memory");
}
__device__ __forceinline__ uint32_t f2tf32(float v) {
    uint32_t r;
    asm("cvt.rna.tf32.f32 %0, %1;" : "=r"(r) : "f"(v));
    return r;
}
__device__ __forceinline__ void mma8(float& c0, float& c1, float& c2, float& c3,
                                     uint32_t a0, uint32_t a1, uint32_t a2, uint32_t a3,
                                     uint32_t b0, uint32_t b1) {
    asm volatile("mma.sync.aligned.m16n8k8.row.col.f32.tf32.tf32.f32 "
                 "{%0,%1,%2,%3},{%4,%5,%6,%7},{%8,%9},{%0,%1,%2,%3};"
                 : "+f"(c0), "+f"(c1), "+f"(c2), "+f"(c3)
                 : "r"(a0), "r"(a1), "r"(a2), "r"(a3), "r"(b0), "r"(b1));
}

// ---------------- weight prep: transpose + tf32 round ----------------
__global__ void wprep_kernel(const float* __restrict__ w) {
    int idx = blockIdx.x * 256 + threadIdx.x;
    if (idx < 165888) {
        int l = idx & 31;
        int r = idx >> 5;
        int oc = r & 63; r >>= 6;
        int t = r % 9;  r /= 9;
        int k1 = r % 3;
        int chunk = r / 3;
        float v = w[((chunk * 64 + oc) * 32 + l) * 27 + k1 * 9 + t];
        W2d[idx] = __uint_as_float(f2tf32(v));
    }
}

// ---------------- main kernel ----------------
__global__ __launch_bounds__(256, 1)
void conv4d_mma_kernel(const float* __restrict__ x,
                       const float* __restrict__ bias,
                       float* __restrict__ out)
{
    extern __shared__ float sm[];
    float* bs = sm;                    // 64 floats
    float* As = sm + 64;               // AFL floats (128B-aligned: 64*4=256)
    float* Bs = sm + 64 + AFL;         // BFL floats
    const uint32_t* Au = (const uint32_t*)As;
    const uint32_t* Bu = (const uint32_t*)Bs;

    const int blk = blockIdx.x;        // b*576 + d0*24 + d1
    const int d1  = blk % DDIM;
    const int t0  = blk / DDIM;
    const int d0  = t0 % DDIM;
    const int b   = t0 / DDIM;

    const int tid   = threadIdx.x;
    const int wid   = tid >> 5;
    const int lane  = tid & 31;
    const int wm    = wid & 3;         // M quarter: rows [wm*160, wm*160+160)
    const int wn    = wid >> 2;        // N half: oc [wn*32, wn*32+32)
    const int laneq = lane >> 2;       // 0..7
    const int lanec = lane & 3;        // 0..3

    if (tid < 64) bs[tid] = bias[tid];
    if (tid < 576) {                   // zero the 18 junk-pad rows once
        int q = 676 + (tid >> 5), l = tid & 31;
        As[q * 32 + (l ^ ((q & 7) << 2))] = 0.0f;
    }

    float cc[10][4][4];
    #pragma unroll
    for (int i = 0; i < 10; i++)
        #pragma unroll
        for (int j = 0; j < 4; j++)
            #pragma unroll
            for (int k = 0; k < 4; k++) cc[i][j][k] = 0.0f;

    // staging constants: this thread owns plane l_st, positions q = q0_st + 8k
    const int l_st  = tid >> 3;
    const int q0_st = tid & 7;
    const int xl_st = l_st ^ (q0_st << 2);   // swizzle xor (q&7 == q0_st for all its q)

    for (int chunk = 0; chunk < 3; chunk++) {
        for (int k1 = 0; k1 < 3; k1++) {
            const int e1 = d1 + k1 - 1;
            if ((unsigned)e1 >= (unsigned)DDIM) continue;

            // ---- stage B (9 taps x 64 oc x 32 l) via cp.async, swizzled ----
            const float* wsrc = W2d + (chunk * 3 + k1) * 18432;
            #pragma unroll
            for (int i = 0; i < 18; i++) {
                const int e4 = (tid + i * 256) * 4;        // float index, 16B granules
                const int tap = e4 >> 11;
                const int rem = e4 & 2047;
                const int oc  = rem >> 5, l0 = rem & 31;
                cpasync16(Bs + tap * 2048 + oc * 32 + (l0 ^ ((oc & 7) << 2)), wsrc + e4);
            }

            // ---- stage A: 676 positions x 32 planes, LDG + cvt.rna + swizzled STS ----
            {
                const int Labs = (d0 + chunk) * 32 + l_st;
                const int cin  = Labs / 26;
                const int e0   = Labs - cin * 26 - 1;
                const bool lok = (unsigned)e0 < (unsigned)DDIM;
                const float* xb = x + (((size_t)(b * 32 + cin) * 24 + (lok ? e0 : 0)) * 24 + e1) * 576;
                int q = q0_st, y = 0, xc = q0_st;
                int sidx = q * 32 + xl_st;
                #pragma unroll 5
                for (int k = 0; k < 85; k++) {
                    if (q < 676) {
                        float v = 0.0f;
                        if (lok && (unsigned)(y - 1) < (unsigned)DDIM &&
                            (unsigned)(xc - 1) < (unsigned)DDIM)
                            v = __ldg(xb + (y - 1) * 24 + (xc - 1));
                        As[sidx] = __uint_as_float(f2tf32(v));
                    }
                    q += 8; sidx += 256;
                    xc += 8; if (xc >= 26) { xc -= 26; y++; }
                }
            }
            asm volatile("cp.async.wait_all;" ::: "memory");
            __syncthreads();

            // ---- compute: 9 taps x 4 ks x (10 m16 x 4 n8) mmas ----
            for (int tap = 0; tap < 9; tap++) {
                const int shift = (tap / 3) * 26 + (tap % 3);
                const int rbase = wm * 160 + shift + laneq;
                const int xr    = (rbase & 7) << 2;
                const int abase = rbase * 32;
                const int tapo  = tap * 2048;
                const int xb2   = laneq << 2;
                for (int ks = 0; ks < 4; ks++) {
                    const int c0  = ks * 8 + lanec;
                    const int cb0 = c0 ^ xb2, cb1 = (c0 + 4) ^ xb2;
                    uint32_t fb0[4], fb1[4];
                    #pragma unroll
                    for (int n8 = 0; n8 < 4; n8++) {
                        const int ob = (wn * 32 + n8 * 8 + laneq) * 32 + tapo;
                        fb0[n8] = Bu[ob + cb0];
                        fb1[n8] = Bu[ob + cb1];
                    }
                    const int ca0 = c0 ^ xr, ca2 = (c0 + 4) ^ xr;
                    #pragma unroll
                    for (int t16 = 0; t16 < 10; t16++) {
                        const int ab = abase + t16 * 512;
                        const uint32_t a0 = Au[ab + ca0];
                        const uint32_t a2 = Au[ab + ca2];
                        const uint32_t a1 = Au[ab + 256 + ca0];
                        const uint32_t a3 = Au[ab + 256 + ca2];
                        #pragma unroll
                        for (int n8 = 0; n8 < 4; n8++)
                            mma8(cc[t16][n8][0], cc[t16][n8][1], cc[t16][n8][2], cc[t16][n8][3],
                                 a0, a1, a2, a3, fb0[n8], fb1[n8]);
                    }
                }
            }
            __syncthreads();   // before next iter overwrites A/B
        }
    }

    // ---- epilogue: bias + store (skip invalid anchors) ----
    const size_t ob = (size_t)b * 21233664 + (size_t)d0 * 13824 + (size_t)d1 * 576;
    #pragma unroll
    for (int t16 = 0; t16 < 10; t16++) {
        const int qa = wm * 160 + t16 * 16 + laneq;
        const int qb = qa + 8;
        const int p2a = qa / 26, p3a = qa - p2a * 26;
        const int p2b = qb / 26, p3b = qb - p2b * 26;
        const bool va = (p2a < DDIM) && (p3a < DDIM);
        const bool vb = (p2b < DDIM) && (p3b < DDIM);
        #pragma unroll
        for (int n8 = 0; n8 < 4; n8++) {
            const int oc = wn * 32 + n8 * 8 + lanec * 2;
            const float bv0 = bs[oc], bv1 = bs[oc + 1];
            float* o0 = out + ob + (size_t)oc * 331776;
            if (va) {
                o0[p2a * 24 + p3a]          = cc[t16][n8][0] + bv0;
                o0[331776 + p2a * 24 + p3a] = cc[t16][n8][1] + bv1;
            }
            if (vb) {
                o0[p2b * 24 + p3b]          = cc[t16][n8][2] + bv0;
                o0[331776 + p2b * 24 + p3b] = cc[t16][n8][3] + bv1;
            }
        }
    }
}

extern "C" void kernel_launch(void* const* d_in, const int* in_sizes, int n_in,
                              void* d_out, int out_size)
{
    const float* x = nullptr;
    const float* w = nullptr;
    const float* bias = nullptr;
    for (int k = 0; k < n_in; k++) {
        if (in_sizes[k] == 2 * 32 * 24 * 24 * 24 * 24) x    = (const float*)d_in[k];
        else if (in_sizes[k] == 3 * 64 * 32 * 27)      w    = (const float*)d_in[k];
        else if (in_sizes[k] == 64)                    bias = (const float*)d_in[k];
    }
    float* out = (float*)d_out;

    wprep_kernel<<<(165888 + 255) / 256, 256>>>(w);

    const int smem_bytes = (64 + AFL + BFL) * 4;   // 162816
    cudaFuncSetAttribute(conv4d_mma_kernel, cudaFuncAttributeMaxDynamicSharedMemorySize, smem_bytes);
    conv4d_mma_kernel<<<2 * 24 * 24, 256, smem_bytes>>>(x, bias, out);
}

// round 9
// speedup vs baseline: 2.6587x; 1.1808x over previous
#include <cuda_runtime.h>
#include <cstdint>

// out[b,o,d0,d1,p2,p3] = bias[o] + sum_{chunk,l,k1,k2,k3} w[chunk,o,l,k1,k2,k3] *
//   xp[b, cin, e0, d1+k1-1, p2+k2-1, p3+k3-1],  Labs=(d0+chunk)*32+l, cin=Labs/26, e0=Labs%26-1
// Implicit GEMM via mma.sync tf32. CTA = (b,d0,d1, M-half): D[320 anchors][64 oc], K=2592.
// Pipelined: B double-buffered via cp.async, A register-prefetched (float4) + STS after compute.

#define DDIM 24
#define AR 426                  // A rows staged (local window + margin)
#define AFL (AR * 32)           // 13632 floats
#define BFL 18432               // floats per B slot (9 taps x 64 oc x 32 l)

__device__ float W2d[165888];   // [(chunk*3+k1)*9+tap][oc][l], tf32-rounded

__device__ __forceinline__ void cpasync16(const float* smem_dst, const float* gsrc) {
    unsigned a = (unsigned)__cvta_generic_to_shared(smem_dst);
    asm volatile("cp.async.cg.shared.global [%0], [%1], 16;" :: "r"(a), "l"(gsrc) : "memory");
}
__device__ __forceinline__ uint32_t f2tf32(float v) {
    uint32_t r;
    asm("cvt.rna.tf32.f32 %0, %1;" : "=r"(r) : "f"(v));
    return r;
}
__device__ __forceinline__ void mma8(float& c0, float& c1, float& c2, float& c3,
                                     uint32_t a0, uint32_t a1, uint32_t a2, uint32_t a3,
                                     uint32_t b0, uint32_t b1) {
    asm volatile("mma.sync.aligned.m16n8k8.row.col.f32.tf32.tf32.f32 "
                 "{%0,%1,%2,%3},{%4,%5,%6,%7},{%8,%9},{%0,%1,%2,%3};"
                 : "+f"(c0), "+f"(c1), "+f"(c2), "+f"(c3)
                 : "r"(a0), "r"(a1), "r"(a2), "r"(a3), "r"(b0), "r"(b1));
}

__global__ void wprep_kernel(const float* __restrict__ w) {
    int idx = blockIdx.x * 256 + threadIdx.x;
    if (idx < 165888) {
        int l = idx & 31;
        int r = idx >> 5;
        int oc = r & 63; r >>= 6;
        int t = r % 9;  r /= 9;
        int k1 = r % 3;
        int chunk = r / 3;
        float v = w[((chunk * 64 + oc) * 32 + l) * 27 + k1 * 9 + t];
        W2d[idx] = __uint_as_float(f2tf32(v));
    }
}

__global__ __launch_bounds__(256, 1)
void conv4d_mma_kernel(const float* __restrict__ x,
                       const float* __restrict__ bias,
                       float* __restrict__ out)
{
    extern __shared__ float sm[];
    float* bs = sm;                         // 64 floats
    float* As = sm + 64;                    // AFL
    float* B0 = sm + 64 + AFL;              // BFL
    float* B1 = B0 + BFL;                   // BFL

    const int blk  = blockIdx.x;            // b*576 + d0*24 + d1
    const int d1   = blk % DDIM;
    const int t0   = blk / DDIM;
    const int d0   = t0 % DDIM;
    const int b    = t0 / DDIM;
    const int half = blockIdx.y;
    const int qoff = half * 320;
    const int y1lo = 11 * half;              // staged interior rows y1 in [y1lo, y1lo+ny)
    const int ny   = 15 - 2 * half;

    const int tid   = threadIdx.x;
    const int wid   = tid >> 5;
    const int lane  = tid & 31;
    const int wm    = wid & 3;               // M slab: local anchors [wm*80, wm*80+80)
    const int wn    = wid >> 2;              // N half: oc [wn*32, wn*32+32)
    const int laneq = lane >> 2;
    const int lanec = lane & 3;
    const int l_st  = tid & 31;              // staging plane (same for all slots)
    const int tq    = tid >> 5;

    if (tid < 64) bs[tid] = bias[tid];

    // ---- zero A complement (borders / junk / unreached rows): iter-invariant ----
    for (int i = tid; i < AFL; i += 256) {
        const int r = i >> 5, l = i & 31;
        const int q = qoff + r;
        const int y = q / 26, xc = q - y * 26;
        const int y1 = y - 1;
        const bool staged = (y1 >= y1lo) && (y1 < y1lo + ny) && (xc >= 1) && (xc <= 24);
        if (!staged) As[r * 32 + (l ^ ((r & 7) << 2))] = 0.0f;
    }

    // ---- valid (chunk,k1) pair list ----
    int prs[9]; int np = 0;
    #pragma unroll
    for (int chunk = 0; chunk < 3; chunk++)
        #pragma unroll
        for (int k1 = 0; k1 < 3; k1++) {
            const int e1 = d1 + k1 - 1;
            if ((unsigned)e1 < (unsigned)DDIM) prs[np++] = chunk * 3 + k1;
        }

    float cc[5][4][4];
    #pragma unroll
    for (int i = 0; i < 5; i++)
        #pragma unroll
        for (int j = 0; j < 4; j++)
            #pragma unroll
            for (int k = 0; k < 4; k++) cc[i][j][k] = 0.0f;

    float4 pay[12];

    // A gmem -> regs (vectorized), zero for invalid plane / unused slot
    auto ldgA = [&](int pr) {
        const int chunk = pr / 3, k1 = pr - 3 * chunk;
        const int e1   = d1 + k1 - 1;
        const int Labs = (d0 + chunk) * 32 + l_st;
        const int cin  = Labs / 26;
        const int e0   = Labs - cin * 26 - 1;
        const bool lok = (unsigned)e0 < (unsigned)DDIM;
        const float* xb = x + (((size_t)(b * 32 + cin) * 24 + (lok ? e0 : 0)) * 24 + e1) * 576;
        #pragma unroll
        for (int s = 0; s < 12; s++) {
            const int v32 = tq + s * 8;
            float4 p = make_float4(0.f, 0.f, 0.f, 0.f);
            if (v32 < ny * 6 && lok) {
                const int y1 = y1lo + v32 / 6;
                const int g  = v32 - 6 * (v32 / 6);
                p = __ldg((const float4*)(xb + y1 * 24 + g * 4));
            }
            pay[s] = p;
        }
    };
    // regs -> A smem (cvt.rna + swizzled STS); zeros for invalid planes keep A correct
    auto stsA = [&]() {
        #pragma unroll
        for (int s = 0; s < 12; s++) {
            const int v32 = tq + s * 8;
            if (v32 < ny * 6) {
                const int y1 = y1lo + v32 / 6;
                const int g  = v32 - 6 * (v32 / 6);
                const int q0 = (y1 + 1) * 26 + g * 4 + 1 - qoff;
                const float vv[4] = {pay[s].x, pay[s].y, pay[s].z, pay[s].w};
                #pragma unroll
                for (int j = 0; j < 4; j++) {
                    const int r = q0 + j;
                    if ((unsigned)r < (unsigned)AR)
                        As[r * 32 + (l_st ^ ((r & 7) << 2))] = __uint_as_float(f2tf32(vv[j]));
                }
            }
        }
    };
    auto stageB = [&](int pr, float* Bd) {
        const float* wsrc = W2d + pr * BFL;
        #pragma unroll
        for (int i = 0; i < 18; i++) {
            const int e4  = (tid + i * 256) * 4;
            const int tap = e4 >> 11;
            const int rem = e4 & 2047;
            const int oc  = rem >> 5, l0 = rem & 31;
            cpasync16(Bd + tap * 2048 + oc * 32 + (l0 ^ ((oc & 7) << 2)), wsrc + e4);
        }
        asm volatile("cp.async.commit_group;" ::: "memory");
    };

    // ---- prologue: stage iter 0 ----
    ldgA(prs[0]);
    stageB(prs[0], B0);
    stsA();
    asm volatile("cp.async.wait_group 0;" ::: "memory");
    __syncthreads();

    // ---- main pipelined loop ----
    for (int it = 0; it < np; it++) {
        const bool more = (it + 1 < np);
        if (more) {
            stageB(prs[it + 1], (it & 1) ? B0 : B1);   // B[next] -> other slot (hidden)
            ldgA(prs[it + 1]);                          // A[next] -> regs (hidden)
        }

        const uint32_t* Bu = (const uint32_t*)((it & 1) ? B1 : B0);
        const uint32_t* Au = (const uint32_t*)As;

        for (int tap = 0; tap < 9; tap++) {
            const int shift = (tap / 3) * 26 + (tap % 3);
            const int rbase = wm * 80 + shift + laneq;
            const int xr    = (rbase & 7) << 2;
            const int abase = rbase * 32;
            const int tapo  = tap * 2048;
            const int xb2   = laneq << 2;
            for (int ks = 0; ks < 4; ks++) {
                const int c0  = ks * 8 + lanec;
                const int cb0 = c0 ^ xb2, cb1 = (c0 + 4) ^ xb2;
                uint32_t fb0[4], fb1[4];
                #pragma unroll
                for (int n8 = 0; n8 < 4; n8++) {
                    const int ob = (wn * 32 + n8 * 8 + laneq) * 32 + tapo;
                    fb0[n8] = Bu[ob + cb0];
                    fb1[n8] = Bu[ob + cb1];
                }
                const int ca0 = c0 ^ xr, ca2 = (c0 + 4) ^ xr;
                #pragma unroll
                for (int t16 = 0; t16 < 5; t16++) {
                    const int ab = abase + t16 * 512;
                    const uint32_t a0 = Au[ab + ca0];
                    const uint32_t a2 = Au[ab + ca2];
                    const uint32_t a1 = Au[ab + 256 + ca0];
                    const uint32_t a3 = Au[ab + 256 + ca2];
                    #pragma unroll
                    for (int n8 = 0; n8 < 4; n8++)
                        mma8(cc[t16][n8][0], cc[t16][n8][1], cc[t16][n8][2], cc[t16][n8][3],
                             a0, a1, a2, a3, fb0[n8], fb1[n8]);
                }
            }
        }

        __syncthreads();                 // all warps done reading A
        if (more) {
            stsA();                      // commit A[next]
            asm volatile("cp.async.wait_group 0;" ::: "memory");  // B[next] landed
        }
        __syncthreads();
    }

    // ---- epilogue: bias + store valid anchors ----
    const size_t ob = (size_t)b * 21233664 + (size_t)d0 * 13824 + (size_t)d1 * 576;
    #pragma unroll
    for (int t16 = 0; t16 < 5; t16++) {
        const int qa = qoff + wm * 80 + t16 * 16 + laneq;
        const int qb = qa + 8;
        const int p2a = qa / 26, p3a = qa - p2a * 26;
        const int p2b = qb / 26, p3b = qb - p2b * 26;
        const bool va = (p2a < DDIM) && (p3a < DDIM);
        const bool vb = (p2b < DDIM) && (p3b < DDIM);
        #pragma unroll
        for (int n8 = 0; n8 < 4; n8++) {
            const int oc = wn * 32 + n8 * 8 + lanec * 2;
            const float bv0 = bs[oc], bv1 = bs[oc + 1];
            float* o0 = out + ob + (size_t)oc * 331776;
            if (va) {
                o0[p2a * 24 + p3a]          = cc[t16][n8][0] + bv0;
                o0[331776 + p2a * 24 + p3a] = cc[t16][n8][1] + bv1;
            }
            if (vb) {
                o0[p2b * 24 + p3b]          = cc[t16][n8][2] + bv0;
                o0[331776 + p2b * 24 + p3b] = cc[t16][n8][3] + bv1;
            }
        }
    }
}

extern "C" void kernel_launch(void* const* d_in, const int* in_sizes, int n_in,
                              void* d_out, int out_size)
{
    const float* x = nullptr;
    const float* w = nullptr;
    const float* bias = nullptr;
    for (int k = 0; k < n_in; k++) {
        if (in_sizes[k] == 2 * 32 * 24 * 24 * 24 * 24) x    = (const float*)d_in[k];
        else if (in_sizes[k] == 3 * 64 * 32 * 27)      w    = (const float*)d_in[k];
        else if (in_sizes[k] == 64)                    bias = (const float*)d_in[k];
    }
    float* out = (float*)d_out;

    wprep_kernel<<<(165888 + 255) / 256, 256>>>(w);

    const int smem_bytes = (64 + AFL + 2 * BFL) * 4;   // 202240
    cudaFuncSetAttribute(conv4d_mma_kernel, cudaFuncAttributeMaxDynamicSharedMemorySize, smem_bytes);
    dim3 grid(2 * 24 * 24, 2);
    conv4d_mma_kernel<<<grid, 256, smem_bytes>>>(x, bias, out);
}

// round 10
// speedup vs baseline: 3.1107x; 1.1700x over previous
#include <cuda_runtime.h>
#include <cstdint>

// out[b,o,d0,d1,p2,p3] = bias[o] + sum_{chunk,l,k1,k2,k3} w[chunk,o,l,k1,k2,k3] *
//   xp[b, cin, e0, d1+k1-1, p2+k2-1, p3+k3-1],  Labs=(d0+chunk)*32+l, cin=Labs/26, e0=Labs%26-1
// Implicit GEMM via mma.sync tf32. CTA = (b,d0,d1, M-half): D[320 anchors][64 oc], K=2592.
// R10: X2d global prepass (tf32, padded, K-major) -> A staging is pure cp.async; A double-buffered.

#define DDIM 24
#define AR 426
#define AFL (AR * 32)            // 13632 floats per A slot
#define BFL 18432                // floats per B slot
#define X2N 26996736             // 2*24*676*832

__device__ float W2d[165888];    // [(chunk*3+k1)*9+tap][oc][l], tf32-rounded
__device__ float X2d[X2N];       // [b][e1][q 676][Labs 832], tf32-rounded, borders zero

__device__ __forceinline__ void cpasync16(const float* smem_dst, const float* gsrc) {
    unsigned a = (unsigned)__cvta_generic_to_shared(smem_dst);
    asm volatile("cp.async.cg.shared.global [%0], [%1], 16;" :: "r"(a), "l"(gsrc) : "memory");
}
__device__ __forceinline__ uint32_t f2tf32(float v) {
    uint32_t r;
    asm("cvt.rna.tf32.f32 %0, %1;" : "=r"(r) : "f"(v));
    return r;
}
__device__ __forceinline__ void mma8(float& c0, float& c1, float& c2, float& c3,
                                     uint32_t a0, uint32_t a1, uint32_t a2, uint32_t a3,
                                     uint32_t b0, uint32_t b1) {
    asm volatile("mma.sync.aligned.m16n8k8.row.col.f32.tf32.tf32.f32 "
                 "{%0,%1,%2,%3},{%4,%5,%6,%7},{%8,%9},{%0,%1,%2,%3};"
                 : "+f"(c0), "+f"(c1), "+f"(c2), "+f"(c3)
                 : "r"(a0), "r"(a1), "r"(a2), "r"(a3), "r"(b0), "r"(b1));
}

// ---------------- prepass: weights ----------------
__global__ void wprep_kernel(const float* __restrict__ w) {
    int idx = blockIdx.x * 256 + threadIdx.x;
    if (idx < 165888) {
        int l = idx & 31;
        int r = idx >> 5;
        int oc = r & 63; r >>= 6;
        int t = r % 9;  r /= 9;
        int k1 = r % 3;
        int chunk = r / 3;
        float v = w[((chunk * 64 + oc) * 32 + l) * 27 + k1 * 9 + t];
        W2d[idx] = __uint_as_float(f2tf32(v));
    }
}

// ---------------- prepass: zero X2d ----------------
__global__ void xzero_kernel() {
    size_t i = (size_t)blockIdx.x * 1024 + threadIdx.x;
    float4 z = make_float4(0.f, 0.f, 0.f, 0.f);
    if (i * 4 < X2N) *(float4*)(X2d + i * 4) = z;
}

// ---------------- prepass: interior transpose x -> X2d ----------------
// block per (b, cin, e1); smem tile [24][577-pad] for bank-safe transpose.
__global__ void xprep_kernel(const float* __restrict__ x) {
    extern __shared__ float sp[];
    const int bid = blockIdx.x;
    const int e1  = bid % 24;
    const int cin = (bid / 24) % 32;
    const int b   = bid / 768;
    const int tid = threadIdx.x;

    const float* base = x + (size_t)(b * 32 + cin) * 331776 + e1 * 576;
    for (int i = tid; i < 13824; i += 256) {
        const int e0  = i / 576;
        const int rem = i - e0 * 576;
        sp[e0 * 577 + rem] = __uint_as_float(f2tf32(__ldg(base + e0 * 13824 + rem)));
    }
    __syncthreads();
    const size_t dbase = (size_t)(b * 24 + e1) * 676 * 832 + cin * 26;
    for (int j = tid; j < 13824; j += 256) {
        const int y    = j / 576;
        const int rem2 = j - y * 576;
        const int z    = rem2 / 24;
        const int e0   = rem2 - z * 24;
        X2d[dbase + (size_t)((y + 1) * 26 + (z + 1)) * 832 + (e0 + 1)] =
            sp[e0 * 577 + y * 24 + z];
    }
}

// ---------------- main kernel ----------------
__global__ __launch_bounds__(256, 1)
void conv4d_mma_kernel(const float* __restrict__ bias,
                       float* __restrict__ out)
{
    extern __shared__ float sm[];
    float* bs = sm;                          // 64 floats
    float* A0 = sm + 64;
    float* A1 = A0 + AFL;
    float* Bs = A1 + AFL;

    const int blk  = blockIdx.x;             // b*576 + d0*24 + d1
    const int d1   = blk % DDIM;
    const int t0   = blk / DDIM;
    const int d0   = t0 % DDIM;
    const int b    = t0 / DDIM;
    const int half = blockIdx.y;
    const int qoff = half * 320;

    const int tid   = threadIdx.x;
    const int wid   = tid >> 5;
    const int lane  = tid & 31;
    const int wm    = wid & 3;
    const int wn    = wid >> 2;
    const int laneq = lane >> 2;
    const int lanec = lane & 3;

    if (tid < 64) bs[tid] = bias[tid];

    // zero junk rows (qglobal >= 676) of BOTH A slots, once
    for (int r = 676 - qoff + (tid >> 5); r < AR; r += 8) {
        A0[r * 32 + lane] = 0.0f;
        A1[r * 32 + lane] = 0.0f;
    }

    // valid (chunk,k1) pairs
    int prs[9]; int np = 0;
    #pragma unroll
    for (int chunk = 0; chunk < 3; chunk++)
        #pragma unroll
        for (int k1 = 0; k1 < 3; k1++) {
            const int e1 = d1 + k1 - 1;
            if ((unsigned)e1 < (unsigned)DDIM) prs[np++] = chunk * 3 + k1;
        }

    float cc[5][4][4];
    #pragma unroll
    for (int i = 0; i < 5; i++)
        #pragma unroll
        for (int j = 0; j < 4; j++)
            #pragma unroll
            for (int k = 0; k < 4; k++) cc[i][j][k] = 0.0f;

    auto stageA = [&](int pr, float* Ad) {
        const int chunk = pr / 3, k1 = pr - 3 * chunk;
        const int e1 = d1 + k1 - 1;
        const float* src = X2d + (size_t)(b * 24 + e1) * 676 * 832 + (d0 + chunk) * 32;
        #pragma unroll
        for (int k = 0; k < 14; k++) {
            const int gid = tid + k * 256;
            if (gid < 3408) {
                const int r = gid >> 3, g = gid & 7;
                const int qg = qoff + r;
                if (qg < 676)
                    cpasync16(Ad + r * 32 + ((g ^ (r & 7)) << 2),
                              src + (size_t)qg * 832 + g * 4);
            }
        }
        asm volatile("cp.async.commit_group;" ::: "memory");
    };
    auto stageB = [&](int pr) {
        const float* wsrc = W2d + pr * BFL;
        #pragma unroll
        for (int i = 0; i < 18; i++) {
            const int e4  = (tid + i * 256) * 4;
            const int tap = e4 >> 11;
            const int rem = e4 & 2047;
            const int oc  = rem >> 5, l0 = rem & 31;
            cpasync16(Bs + tap * 2048 + oc * 32 + (l0 ^ ((oc & 7) << 2)), wsrc + e4);
        }
        asm volatile("cp.async.commit_group;" ::: "memory");
    };

    // prologue
    stageA(prs[0], A0);
    stageB(prs[0]);
    asm volatile("cp.async.wait_group 0;" ::: "memory");
    __syncthreads();

    const uint32_t* Bu = (const uint32_t*)Bs;

    for (int it = 0; it < np; it++) {
        const bool more = (it + 1 < np);
        if (more) stageA(prs[it + 1], (it & 1) ? A0 : A1);   // hidden behind compute

        const uint32_t* Au = (const uint32_t*)((it & 1) ? A1 : A0);

        for (int tap = 0; tap < 9; tap++) {
            const int shift = (tap / 3) * 26 + (tap % 3);
            const int rbase = wm * 80 + shift + laneq;
            const int xr    = (rbase & 7) << 2;
            const int abase = rbase * 32;
            const int tapo  = tap * 2048;
            const int xb2   = laneq << 2;
            for (int ks = 0; ks < 4; ks++) {
                const int c0  = ks * 8 + lanec;
                const int cb0 = c0 ^ xb2, cb1 = (c0 + 4) ^ xb2;
                uint32_t fb0[4], fb1[4];
                #pragma unroll
                for (int n8 = 0; n8 < 4; n8++) {
                    const int ob = (wn * 32 + n8 * 8 + laneq) * 32 + tapo;
                    fb0[n8] = Bu[ob + cb0];
                    fb1[n8] = Bu[ob + cb1];
                }
                const int ca0 = c0 ^ xr, ca2 = (c0 + 4) ^ xr;
                #pragma unroll
                for (int t16 = 0; t16 < 5; t16++) {
                    const int ab = abase + t16 * 512;
                    const uint32_t a0 = Au[ab + ca0];
                    const uint32_t a2 = Au[ab + ca2];
                    const uint32_t a1 = Au[ab + 256 + ca0];
                    const uint32_t a3 = Au[ab + 256 + ca2];
                    #pragma unroll
                    for (int n8 = 0; n8 < 4; n8++)
                        mma8(cc[t16][n8][0], cc[t16][n8][1], cc[t16][n8][2], cc[t16][n8][3],
                             a0, a1, a2, a3, fb0[n8], fb1[n8]);
                }
            }
        }

        __syncthreads();                     // everyone done with B (and A[cur])
        if (more) {
            stageB(prs[it + 1]);             // exposed: ~L2 latency only
            asm volatile("cp.async.wait_group 0;" ::: "memory");
            __syncthreads();
        }
    }

    // epilogue
    const size_t ob = (size_t)b * 21233664 + (size_t)d0 * 13824 + (size_t)d1 * 576;
    #pragma unroll
    for (int t16 = 0; t16 < 5; t16++) {
        const int qa = qoff + wm * 80 + t16 * 16 + laneq;
        const int qb = qa + 8;
        const int p2a = qa / 26, p3a = qa - p2a * 26;
        const int p2b = qb / 26, p3b = qb - p2b * 26;
        const bool va = (p2a < DDIM) && (p3a < DDIM);
        const bool vb = (p2b < DDIM) && (p3b < DDIM);
        #pragma unroll
        for (int n8 = 0; n8 < 4; n8++) {
            const int oc = wn * 32 + n8 * 8 + lanec * 2;
            const float bv0 = bs[oc], bv1 = bs[oc + 1];
            float* o0 = out + ob + (size_t)oc * 331776;
            if (va) {
                o0[p2a * 24 + p3a]          = cc[t16][n8][0] + bv0;
                o0[331776 + p2a * 24 + p3a] = cc[t16][n8][1] + bv1;
            }
            if (vb) {
                o0[p2b * 24 + p3b]          = cc[t16][n8][2] + bv0;
                o0[331776 + p2b * 24 + p3b] = cc[t16][n8][3] + bv1;
            }
        }
    }
}

extern "C" void kernel_launch(void* const* d_in, const int* in_sizes, int n_in,
                              void* d_out, int out_size)
{
    const float* x = nullptr;
    const float* w = nullptr;
    const float* bias = nullptr;
    for (int k = 0; k < n_in; k++) {
        if (in_sizes[k] == 2 * 32 * 24 * 24 * 24 * 24) x    = (const float*)d_in[k];
        else if (in_sizes[k] == 3 * 64 * 32 * 27)      w    = (const float*)d_in[k];
        else if (in_sizes[k] == 64)                    bias = (const float*)d_in[k];
    }
    float* out = (float*)d_out;

    wprep_kernel<<<(165888 + 255) / 256, 256>>>(w);
    xzero_kernel<<<(X2N / 4 + 1023) / 1024, 1024>>>();
    const int xp_smem = 24 * 577 * 4;   // 55392
    cudaFuncSetAttribute(xprep_kernel, cudaFuncAttributeMaxDynamicSharedMemorySize, xp_smem);
    xprep_kernel<<<2 * 32 * 24, 256, xp_smem>>>(x);

    const int smem_bytes = (64 + 2 * AFL + BFL) * 4;   // 183040
    cudaFuncSetAttribute(conv4d_mma_kernel, cudaFuncAttributeMaxDynamicSharedMemorySize, smem_bytes);
    dim3 grid(2 * 24 * 24, 2);
    conv4d_mma_kernel<<<grid, 256, smem_bytes>>>(bias, out);
}

// round 11
// speedup vs baseline: 5.2941x; 1.7019x over previous
#include <cuda_runtime.h>
#include <cuda_fp16.h>
#include <cstdint>

// out[b,o,d0,d1,p2,p3] = bias[o] + sum_{chunk,l,k1,k2,k3} w[chunk,o,l,k1,k2,k3] *
//   xp[b, cin, e0, d1+k1-1, p2+k2-1, p3+k3-1],  Labs=(d0+chunk)*32+l, cin=Labs/26, e0=Labs%26-1
// Implicit GEMM via mma.sync m16n8k16 fp16 (fp32 accum). CTA = (b,d0,d1, M-half).
// fp16 prepass tensors; A and B both double-buffered via cp.async -> zero exposed staging.

#define DDIM 24
#define AR 374                   // A rows per slot (320 anchors + 54 shift margin)
#define ASL 5984                 // u32 per A slot (AR * 16)
#define BSL 9216                 // u32 per B slot (9 taps * 64 oc * 16)
#define X2N 26996736             // halves: 2*24*676*832

__device__ __align__(16) __half W2h[165888];  // [pr][oc 64][l 32] fp16
__device__ __align__(16) __half X2h[X2N];     // [b][e1][q 676][Labs 832] fp16, borders zero

__device__ __forceinline__ void cpasync8(const uint32_t* smem_dst, const __half* gsrc) {
    unsigned a = (unsigned)__cvta_generic_to_shared(smem_dst);
    asm volatile("cp.async.ca.shared.global [%0], [%1], 8;" :: "r"(a), "l"(gsrc) : "memory");
}
__device__ __forceinline__ void mma16(float& c0, float& c1, float& c2, float& c3,
                                      uint32_t a0, uint32_t a1, uint32_t a2, uint32_t a3,
                                      uint32_t b0, uint32_t b1) {
    asm volatile("mma.sync.aligned.m16n8k16.row.col.f32.f16.f16.f32 "
                 "{%0,%1,%2,%3},{%4,%5,%6,%7},{%8,%9},{%0,%1,%2,%3};"
                 : "+f"(c0), "+f"(c1), "+f"(c2), "+f"(c3)
                 : "r"(a0), "r"(a1), "r"(a2), "r"(a3), "r"(b0), "r"(b1));
}

// ---------------- prepass: weights ----------------
__global__ void wprep_kernel(const float* __restrict__ w) {
    int idx = blockIdx.x * 256 + threadIdx.x;
    if (idx < 165888) {
        int l = idx & 31;
        int r = idx >> 5;
        int oc = r & 63; r >>= 6;
        int t = r % 9;  r /= 9;
        int k1 = r % 3;
        int chunk = r / 3;
        W2h[idx] = __float2half_rn(w[((chunk * 64 + oc) * 32 + l) * 27 + k1 * 9 + t]);
    }
}

// ---------------- prepass: zero X2h ----------------
__global__ void xzero_kernel() {
    size_t i = (size_t)blockIdx.x * 1024 + threadIdx.x;
    if (i < X2N / 8) {
        uint4 z = make_uint4(0, 0, 0, 0);
        ((uint4*)X2h)[i] = z;
    }
}

// ---------------- prepass: interior transpose x -> X2h ----------------
__global__ void xprep_kernel(const float* __restrict__ x) {
    extern __shared__ float sp[];
    const int bid = blockIdx.x;
    const int e1  = bid % 24;
    const int cin = (bid / 24) % 32;
    const int b   = bid / 768;
    const int tid = threadIdx.x;

    const float* base = x + (size_t)(b * 32 + cin) * 331776 + e1 * 576;
    for (int i = tid; i < 13824; i += 256) {
        const int e0  = i / 576;
        const int rem = i - e0 * 576;
        sp[e0 * 577 + rem] = __ldg(base + e0 * 13824 + rem);
    }
    __syncthreads();
    const size_t dbase = (size_t)(b * 24 + e1) * 562432 + cin * 26;
    for (int j = tid; j < 13824; j += 256) {
        const int y    = j / 576;
        const int rem2 = j - y * 576;
        const int z    = rem2 / 24;
        const int e0   = rem2 - z * 24;
        X2h[dbase + (size_t)((y + 1) * 26 + (z + 1)) * 832 + (e0 + 1)] =
            __float2half_rn(sp[e0 * 577 + y * 24 + z]);
    }
}

// ---------------- main kernel ----------------
__global__ __launch_bounds__(256, 1)
void conv4d_mma_kernel(const float* __restrict__ bias,
                       float* __restrict__ out)
{
    extern __shared__ float sm[];
    float*    bs  = sm;                       // 64 floats
    uint32_t* A0u = (uint32_t*)(sm + 64);
    uint32_t* A1u = A0u + ASL;
    uint32_t* B0u = A1u + ASL;
    uint32_t* B1u = B0u + BSL;

    const int blk  = blockIdx.x;              // b*576 + d0*24 + d1
    const int d1   = blk % DDIM;
    const int t0   = blk / DDIM;
    const int d0   = t0 % DDIM;
    const int b    = t0 / DDIM;
    const int half = blockIdx.y;
    const int qoff = half * 320;

    const int tid   = threadIdx.x;
    const int wid   = tid >> 5;
    const int lane  = tid & 31;
    const int wm    = wid & 3;                // M slab: local anchors [wm*80, +80)
    const int wn    = wid >> 2;               // N half: oc [wn*32, +32)
    const int laneq = lane >> 2;
    const int lanec = lane & 3;

    if (tid < 64) bs[tid] = bias[tid];

    // zero junk rows (qglobal >= 676) of both A slots, once
    {
        const int jstart = 676 - qoff;        // 676 (none) or 356
        if (jstart < AR) {
            for (int i = jstart * 16 + tid; i < AR * 16; i += 256) {
                A0u[i] = 0u;
                A1u[i] = 0u;
            }
        }
    }

    // valid (chunk,k1) pairs
    int prs[9]; int np = 0;
    #pragma unroll
    for (int chunk = 0; chunk < 3; chunk++)
        #pragma unroll
        for (int k1 = 0; k1 < 3; k1++) {
            const int e1 = d1 + k1 - 1;
            if ((unsigned)e1 < (unsigned)DDIM) prs[np++] = chunk * 3 + k1;
        }

    float cc[5][4][4];
    #pragma unroll
    for (int i = 0; i < 5; i++)
        #pragma unroll
        for (int j = 0; j < 4; j++)
            #pragma unroll
            for (int k = 0; k < 4; k++) cc[i][j][k] = 0.0f;

    auto stageA = [&](int pr, uint32_t* Ad) {
        const int chunk = pr / 3, k1 = pr - 3 * chunk;
        const int e1 = d1 + k1 - 1;
        const __half* src = X2h + (size_t)(b * 24 + e1) * 562432 + (d0 + chunk) * 32;
        #pragma unroll
        for (int k = 0; k < 12; k++) {
            const int gid = tid + k * 256;
            if (gid < AR * 8) {
                const int r = gid >> 3, g = gid & 7;
                const int qg = qoff + r;
                if (qg < 676)
                    cpasync8(Ad + r * 16 + ((g * 2) ^ ((r & 7) << 1)),
                             src + (size_t)qg * 832 + g * 4);
            }
        }
    };
    auto stageB = [&](int pr, uint32_t* Bd) {
        const __half* wsrc = W2h + pr * 18432;
        #pragma unroll
        for (int i = 0; i < 18; i++) {
            const int gid = tid + i * 256;    // < 4608
            const int tap = gid >> 9, rem = gid & 511;
            const int oc  = rem >> 3, g = rem & 7;
            cpasync8(Bd + tap * 1024 + oc * 16 + ((g * 2) ^ ((oc & 7) << 1)),
                     wsrc + tap * 2048 + oc * 32 + g * 4);
        }
    };

    // prologue: stage iter 0
    stageA(prs[0], A0u);
    stageB(prs[0], B0u);
    asm volatile("cp.async.commit_group;" ::: "memory");
    asm volatile("cp.async.wait_group 0;" ::: "memory");
    __syncthreads();

    for (int it = 0; it < np; it++) {
        const bool more = (it + 1 < np);
        if (more) {                            // hidden behind compute
            stageA(prs[it + 1], (it & 1) ? A0u : A1u);
            stageB(prs[it + 1], (it & 1) ? B0u : B1u);
            asm volatile("cp.async.commit_group;" ::: "memory");
        }

        const uint32_t* Au = (it & 1) ? A1u : A0u;
        const uint32_t* Bu = (it & 1) ? B1u : B0u;

        for (int tap = 0; tap < 9; tap++) {
            const int shift = (tap / 3) * 26 + (tap % 3);
            const int rbase = wm * 80 + shift + laneq;
            const int xr    = (rbase & 7) << 1;
            const int arow  = rbase * 16;
            const int tapo  = tap * 1024;
            const int xb    = laneq << 1;
            #pragma unroll
            for (int ks = 0; ks < 2; ks++) {
                const int c0 = ks * 8 + lanec;
                uint32_t fb0[4], fb1[4];
                #pragma unroll
                for (int n8 = 0; n8 < 4; n8++) {
                    const int ob = tapo + (wn * 32 + n8 * 8 + laneq) * 16;
                    fb0[n8] = Bu[ob + (c0 ^ xb)];
                    fb1[n8] = Bu[ob + ((c0 + 4) ^ xb)];
                }
                const int ca0 = c0 ^ xr, ca2 = (c0 + 4) ^ xr;
                #pragma unroll
                for (int t16 = 0; t16 < 5; t16++) {
                    const int ab = arow + t16 * 256;
                    const uint32_t a0 = Au[ab + ca0];
                    const uint32_t a1 = Au[ab + 128 + ca0];
                    const uint32_t a2 = Au[ab + ca2];
                    const uint32_t a3 = Au[ab + 128 + ca2];
                    #pragma unroll
                    for (int n8 = 0; n8 < 4; n8++)
                        mma16(cc[t16][n8][0], cc[t16][n8][1], cc[t16][n8][2], cc[t16][n8][3],
                              a0, a1, a2, a3, fb0[n8], fb1[n8]);
                }
            }
        }

        if (more) asm volatile("cp.async.wait_group 0;" ::: "memory");
        __syncthreads();
    }

    // epilogue: bias + store valid anchors
    const size_t ob = (size_t)b * 21233664 + (size_t)d0 * 13824 + (size_t)d1 * 576;
    #pragma unroll
    for (int t16 = 0; t16 < 5; t16++) {
        const int qa = qoff + wm * 80 + t16 * 16 + laneq;
        const int qb = qa + 8;
        const int p2a = qa / 26, p3a = qa - p2a * 26;
        const int p2b = qb / 26, p3b = qb - p2b * 26;
        const bool va = (p2a < DDIM) && (p3a < DDIM);
        const bool vb = (p2b < DDIM) && (p3b < DDIM);
        #pragma unroll
        for (int n8 = 0; n8 < 4; n8++) {
            const int oc = wn * 32 + n8 * 8 + lanec * 2;
            const float bv0 = bs[oc], bv1 = bs[oc + 1];
            float* o0 = out + ob + (size_t)oc * 331776;
            if (va) {
                o0[p2a * 24 + p3a]          = cc[t16][n8][0] + bv0;
                o0[331776 + p2a * 24 + p3a] = cc[t16][n8][1] + bv1;
            }
            if (vb) {
                o0[p2b * 24 + p3b]          = cc[t16][n8][2] + bv0;
                o0[331776 + p2b * 24 + p3b] = cc[t16][n8][3] + bv1;
            }
        }
    }
}

extern "C" void kernel_launch(void* const* d_in, const int* in_sizes, int n_in,
                              void* d_out, int out_size)
{
    const float* x = nullptr;
    const float* w = nullptr;
    const float* bias = nullptr;
    for (int k = 0; k < n_in; k++) {
        if (in_sizes[k] == 2 * 32 * 24 * 24 * 24 * 24) x    = (const float*)d_in[k];
        else if (in_sizes[k] == 3 * 64 * 32 * 27)      w    = (const float*)d_in[k];
        else if (in_sizes[k] == 64)                    bias = (const float*)d_in[k];
    }
    float* out = (float*)d_out;

    wprep_kernel<<<(165888 + 255) / 256, 256>>>(w);
    xzero_kernel<<<(X2N / 8 + 1023) / 1024, 1024>>>();
    const int xp_smem = 24 * 577 * 4;   // 55392
    cudaFuncSetAttribute(xprep_kernel, cudaFuncAttributeMaxDynamicSharedMemorySize, xp_smem);
    xprep_kernel<<<2 * 32 * 24, 256, xp_smem>>>(x);

    const int smem_bytes = 64 * 4 + (2 * ASL + 2 * BSL) * 4;   // 121856
    cudaFuncSetAttribute(conv4d_mma_kernel, cudaFuncAttributeMaxDynamicSharedMemorySize, smem_bytes);
    dim3 grid(2 * 24 * 24, 2);
    conv4d_mma_kernel<<<grid, 256, smem_bytes>>>(bias, out);
}